// round 2
// baseline (speedup 1.0000x reference)
#include <cuda_runtime.h>

// Problem constants (fixed by setup_inputs)
#define B_    4
#define C_    256
#define H_    256
#define W_    512
#define FS    14
#define NP    (FS*FS)        // 196
#define NROI  400            // B * MAXLOAD
#define HW    (H_*W_)        // 131072
#define HB    (B_*H_)        // 1024 stacked rows

#define CH        8          // channels per smem chunk
#define SPANF     516        // padded floats per smem row (max needed = 512)
#define THREADS   256
#define NBLK_MAIN (NROI*FS)  // 5600 blocks: one per (roi, grid-row i)

static const long OUT_MAIN = (long)NROI * C_ * NP;   // 20,070,400

__global__ __launch_bounds__(THREADS)
void pooler_span_kernel(const float*  __restrict__ feat,
                        const float*  __restrict__ rois,
                        float*        __restrict__ out,
                        long out_size)
{
    __shared__ __align__(16) float tile[CH][2][SPANF];
    __shared__ int   sx0[FS];
    __shared__ float swx[FS];
    __shared__ int   sw_start;   // first float4 word of span (within a row)
    __shared__ int   sw_end;     // last  float4 word of span

    const int blk = blockIdx.x;
    const int tid = threadIdx.x;

    // Tail blocks: write val_bind (k/100) past the main output.
    if (blk >= NBLK_MAIN) {
        long k   = (long)(blk - NBLK_MAIN) * THREADS + tid;
        long idx = OUT_MAIN + k;
        if (idx < out_size) out[idx] = (float)((int)(k / 100));
        return;
    }

    const int n = blk / FS;
    const int i = blk - n * FS;
    const int b = n / 100;                      // roi's batch

    const float4 r = reinterpret_cast<const float4*>(rois)[n];
    const float inv13 = 1.0f / 13.0f;

    // y coordinates: constant over the whole block (depend only on i)
    float scaley = r.w - r.y;
    float biasy  = r.y + (float)b * 1024.0f;    // image_height
    float gridy  = ((float)i * inv13 * scaley + biasy) * 0.25f;   // /shrink_scale
    float gy = (gridy * (1.0f / (HB - 1)) - 0.5f) * 2.0f;
    float py = ((gy + 1.0f) * (float)HB - 1.0f) * 0.5f;
    py = fminf(fmaxf(py, 0.0f), (float)(HB - 1));
    float y0f = floorf(py);
    float wy  = py - y0f;
    int y0 = (int)y0f;
    int y1 = min(y0 + 1, HB - 1);

    // x coordinates: 14 sample columns, precomputed once (monotonic in j)
    if (tid < FS) {
        int j = tid;
        float scalex = r.z - r.x;
        float gridx  = ((float)j * inv13 * scalex + r.x) * 0.25f;
        float gx = (gridx * (1.0f / (W_ - 1)) - 0.5f) * 2.0f;
        float px = ((gx + 1.0f) * (float)W_ - 1.0f) * 0.5f;
        px = fminf(fmaxf(px, 0.0f), (float)(W_ - 1));
        float x0f = floorf(px);
        int   x0  = (int)x0f;
        sx0[j] = x0;
        swx[j] = px - x0f;
        if (j == 0)      sw_start = x0 >> 2;
        if (j == FS - 1) sw_end   = min(x0 + 1, W_ - 1) >> 2;
    }
    __syncthreads();

    const int w4s = sw_start;
    const int nw4 = sw_end - w4s + 1;           // float4 words per row (<=128)

    // feats view (C, B*H, W): row base for y in stacked coords
    const long rb0 = ((long)(y0 >> 8) * C_) * HW + (long)(y0 & 255) * W_;
    const long rb1 = ((long)(y1 >> 8) * C_) * HW + (long)(y1 & 255) * W_;
    const float4* f4 = reinterpret_cast<const float4*>(feat);
    const long rb0w = (rb0 >> 2) + w4s;
    const long rb1w = (rb1 >> 2) + w4s;
    const float omwy = 1.0f - wy;
    const int  xoff  = w4s << 2;

    for (int cc = 0; cc < C_; cc += CH) {
        // stage CH channels x 2 rows x span, coalesced float4 loads
        const int total = CH * 2 * nw4;
        for (int idx = tid; idx < total; idx += THREADS) {
            int row = idx / nw4;
            int off = idx - row * nw4;
            int cl  = row >> 1;
            long base = ((row & 1) ? rb1w : rb0w) + (long)(cc + cl) * (HW / 4);
            float4 v = __ldg(f4 + base + off);
            *reinterpret_cast<float4*>(&tile[cl][row & 1][off << 2]) = v;
        }
        __syncthreads();

        if (tid < CH * FS) {
            int cl = tid / FS;
            int j  = tid - cl * FS;
            int x0 = sx0[j];
            float wx = swx[j];
            int o0 = x0 - xoff;
            int o1 = min(x0 + 1, W_ - 1) - xoff;
            float f00 = tile[cl][0][o0];
            float f01 = tile[cl][0][o1];
            float f10 = tile[cl][1][o0];
            float f11 = tile[cl][1][o1];
            float omwx = 1.0f - wx;
            float v = (f00 * omwx + f01 * wx) * omwy
                    + (f10 * omwx + f11 * wx) * wy;
            out[(((long)n * C_ + (cc + cl)) * FS + i) * FS + j] = v;
        }
        __syncthreads();
    }
}

extern "C" void kernel_launch(void* const* d_in, const int* in_sizes, int n_in,
                              void* d_out, int out_size)
{
    const float* feat = (const float*)d_in[0];
    const float* rois = (const float*)d_in[1];
    float* out = (float*)d_out;

    long tail = (long)out_size - OUT_MAIN;
    int tail_blocks = tail > 0 ? (int)((tail + THREADS - 1) / THREADS) : 0;

    pooler_span_kernel<<<NBLK_MAIN + tail_blocks, THREADS>>>(
        feat, rois, out, (long)out_size);
}

// round 3
// speedup vs baseline: 3.6093x; 3.6093x over previous
#include <cuda_runtime.h>

// Problem constants (fixed by setup_inputs)
#define B_    4
#define C_    256
#define H_    256
#define W_    512
#define FS    14
#define NP    (FS*FS)        // 196
#define NROI  400            // B * MAXLOAD
#define HW    (H_*W_)        // 131072
#define HB    (B_*H_)        // 1024 stacked rows
#define KCH   4              // channels per thread

#define THREADS 256

static const long OUT_MAIN   = (long)NROI * C_ * NP;      // 20,070,400
#define MAIN_THREADS (NROI * (C_ / KCH) * NP)             // 5,017,600
#define MAIN_BLOCKS  (MAIN_THREADS / THREADS)             // 19,600 (exact)

__global__ __launch_bounds__(THREADS)
void pooler_k4_kernel(const float* __restrict__ feat,
                      const float* __restrict__ rois,
                      float*       __restrict__ out,
                      long out_size)
{
    int t = blockIdx.x * THREADS + threadIdx.x;

    // Tail: val_bind = repeat(arange(B), MAXLOAD) appended after main output.
    if (t >= MAIN_THREADS) {
        long k   = (long)(t - MAIN_THREADS);
        long idx = OUT_MAIN + k;
        if (idx < out_size) out[idx] = (float)((int)(k / 100));
        return;
    }

    // t -> (n, cq, p) with p fastest (coalesced loads/stores within a warp)
    int p  = t % NP;
    int q  = t / NP;
    int cq = q % (C_ / KCH);
    int n  = q / (C_ / KCH);
    int c  = cq * KCH;
    int i  = p / FS;
    int j  = p - i * FS;
    int b  = n / 100;                         // roi's batch

    const float4 r = reinterpret_cast<const float4*>(rois)[n];
    const float inv13 = 1.0f / 13.0f;

    float scalex = r.z - r.x;
    float scaley = r.w - r.y;
    float biasy  = r.y + (float)b * 1024.0f;  // image_height

    float gridx = ((float)j * inv13 * scalex + r.x)  * 0.25f;  // /shrink_scale
    float gridy = ((float)i * inv13 * scaley + biasy) * 0.25f;

    // normalized-grid round trip, exactly as reference
    float gx = (gridx * (1.0f / (W_ - 1)) - 0.5f) * 2.0f;
    float gy = (gridy * (1.0f / (HB - 1)) - 0.5f) * 2.0f;
    float px = ((gx + 1.0f) * (float)W_ - 1.0f) * 0.5f;
    float py = ((gy + 1.0f) * (float)HB - 1.0f) * 0.5f;
    px = fminf(fmaxf(px, 0.0f), (float)(W_ - 1));
    py = fminf(fmaxf(py, 0.0f), (float)(HB - 1));

    float x0f = floorf(px);
    float y0f = floorf(py);
    float wx  = px - x0f;
    float wy  = py - y0f;
    int x0 = (int)x0f;
    int y0 = (int)y0f;
    int x1 = min(x0 + 1, W_ - 1);
    int y1 = min(y0 + 1, HB - 1);

    // feats view (C, B*H, W); element indices fit in int32 (max ~134M)
    int a0 = ((y0 >> 8) * C_ + c) * HW + (y0 & 255) * W_;
    int a1 = ((y1 >> 8) * C_ + c) * HW + (y1 & 255) * W_;

    // Front-batched independent loads: 16 LDG.32 in flight (MLP=16)
    float f00[KCH], f01[KCH], f10[KCH], f11[KCH];
#pragma unroll
    for (int k = 0; k < KCH; k++) {
        int o = k * HW;
        f00[k] = __ldg(feat + a0 + o + x0);
        f01[k] = __ldg(feat + a0 + o + x1);
        f10[k] = __ldg(feat + a1 + o + x0);
        f11[k] = __ldg(feat + a1 + o + x1);
    }

    float omwx = 1.0f - wx;
    float omwy = 1.0f - wy;
    long ob = ((long)(n * C_ + c)) * NP + p;
#pragma unroll
    for (int k = 0; k < KCH; k++) {
        float v = (f00[k] * omwx + f01[k] * wx) * omwy
                + (f10[k] * omwx + f11[k] * wx) * wy;
        out[ob + (long)k * NP] = v;
    }
}

extern "C" void kernel_launch(void* const* d_in, const int* in_sizes, int n_in,
                              void* d_out, int out_size)
{
    const float* feat = (const float*)d_in[0];
    const float* rois = (const float*)d_in[1];
    float* out = (float*)d_out;

    long tail = (long)out_size - OUT_MAIN;
    int tail_blocks = tail > 0 ? (int)((tail + THREADS - 1) / THREADS) : 0;

    pooler_k4_kernel<<<MAIN_BLOCKS + tail_blocks, THREADS>>>(
        feat, rois, out, (long)out_size);
}